// round 14
// baseline (speedup 1.0000x reference)
#include <cuda_runtime.h>
#include <cuda_fp16.h>
#include <cstdint>
#include <mma.h>
#include <math.h>

using namespace nvcuda;

#define S   512
#define T   16384
#define D   512
#define DFF 2048
#define SEG (T / S)          // 32 frames per segment
#define G   4                // queries per attention block

// -------- scratch (allocation-free: __device__ globals) --------
__device__ __half g_rctx_h[S * D];            // relu(ctx) fp16
__device__ __half g_xh[S * D];                // x fp16 (GEMM A)
__device__ __half g_h[S * DFF];               // relu FFN hidden fp16
__device__ __half g_wh[D * D + DFF * D + D * DFF];  // fp16 weights
__device__ float  g_x[S * D];                 // x fp32 (residual)
__device__ float  g_acc[2 * S * D];           // accumulators: [0]=tgt2 path, [1]=ffn path

// ============================================================
// cp.async helpers
// ============================================================
__device__ __forceinline__ void cp_async16(void* sm, const void* gm) {
    unsigned int a = (unsigned int)__cvta_generic_to_shared(sm);
    asm volatile("cp.async.cg.shared.global [%0], [%1], 16;" :: "r"(a), "l"(gm) : "memory");
}
__device__ __forceinline__ void cp_commit() {
    asm volatile("cp.async.commit_group;" ::: "memory");
}
__device__ __forceinline__ void cp_wait2() {
    asm volatile("cp.async.wait_group 2;" ::: "memory");
}

__device__ __forceinline__ float dot4(float4 a, float4 b) {
    return fmaf(a.x, b.x, fmaf(a.y, b.y, fmaf(a.z, b.z, a.w * b.w)));
}

// ============================================================
// cvt kernel: fp32->fp16 weights (mats 0..2) and
// mat 3: acc[0] = tgt + bt2  (gemm2 accumulator init)
// ============================================================
__global__ __launch_bounds__(256) void cvt_kernel(
    const float* __restrict__ w0, const float* __restrict__ w1,
    const float* __restrict__ w2, const float* __restrict__ tgt,
    const float* __restrict__ bt2)
{
    const int mat = blockIdx.y;
    if (mat == 3) {
        const float4* t4 = (const float4*)tgt;
        const float4* b4 = (const float4*)bt2;
        float4* a4 = (float4*)g_acc;
        for (int i = blockIdx.x * 256 + threadIdx.x; i < S * D / 4; i += gridDim.x * 256) {
            float4 t = t4[i], b = b4[i & 127];
            a4[i] = make_float4(t.x + b.x, t.y + b.y, t.z + b.z, t.w + b.w);
        }
        return;
    }
    const float2* src;
    __half2* dst;
    int n2;
    if (mat == 0) { src = (const float2*)w0; dst = (__half2*)g_wh;                 n2 = D * D / 2; }
    else if (mat == 1) { src = (const float2*)w1; dst = (__half2*)(g_wh + D * D);  n2 = DFF * D / 2; }
    else { src = (const float2*)w2; dst = (__half2*)(g_wh + D * D + DFF * D);      n2 = D * DFF / 2; }
    for (int i = blockIdx.x * 256 + threadIdx.x; i < n2; i += gridDim.x * 256)
        dst[i] = __float22half2_rn(src[i]);
}

// ============================================================
// Kernel 1: banded attention -> relu(ctx) fp16. (R13, proven)
// ============================================================
__global__ __launch_bounds__(512) void attn_kernel(
    const float* __restrict__ tgt, const float* __restrict__ mem,
    const float* __restrict__ pos, const float* __restrict__ qpos,
    const int*   __restrict__ aidx)
{
    const int blk  = blockIdx.x;
    const int tid  = threadIdx.x;
    const int warp = tid >> 5, lane = tid & 31;
    const int q0   = blk * G;

    const int t0 = max(0, q0 - 1) * SEG;
    const int t1 = min(S, q0 + G + 1) * SEG;
    const int nf = t1 - t0;                      // 160 or 192

    __shared__ float4 qs[G][D / 4];
    __shared__ float  sp[G][3 * SEG];            // per-query 96-slot window
    __shared__ float  invd[G];

    for (int i = tid; i < G * 3 * SEG; i += 512)
        ((float*)sp)[i] = -INFINITY;
    {
        const int qi = tid >> 7, d4 = tid & 127;
        float4 tv = ((const float4*)tgt)[(size_t)(q0 + qi) * (D / 4) + d4];
        float4 pv = ((const float4*)qpos)[(size_t)(q0 + qi) * (D / 4) + d4];
        qs[qi][d4] = make_float4(tv.x + pv.x, tv.y + pv.y, tv.z + pv.z, tv.w + pv.w);
    }
    __syncthreads();

    const float scale = 0.04419417382415922f;  // 1/sqrt(512)

    for (int base = warp; base < nf; base += 32) {
        const int fA = base;
        const int fB = base + 16;
        const bool hasB = fB < nf;
        const int tA = t0 + fA;
        const int tB = t0 + (hasB ? fB : fA);
        const int aA = aidx[tA];
        const int aB = aidx[tB];
        const int rA = aA - 1 - q0;
        const int rB = aB - 1 - q0;
        const int qA0 = min(max(rA, 0), G - 1), qA1 = min(max(rA + 1, 0), G - 1), qA2 = min(max(rA + 2, 0), G - 1);
        const int qB0 = min(max(rB, 0), G - 1), qB1 = min(max(rB + 1, 0), G - 1), qB2 = min(max(rB + 2, 0), G - 1);

        const float4* mA = (const float4*)mem + (size_t)tA * (D / 4);
        const float4* pA = (const float4*)pos + (size_t)tA * (D / 4);
        const float4* mB = (const float4*)mem + (size_t)tB * (D / 4);
        const float4* pB = (const float4*)pos + (size_t)tB * (D / 4);

        float dA0 = 0.f, dA1 = 0.f, dA2 = 0.f;
        float dB0 = 0.f, dB1 = 0.f, dB2 = 0.f;
        #pragma unroll
        for (int i = 0; i < 4; i++) {
            const int d4 = lane + 32 * i;
            float4 ma = mA[d4], pa = pA[d4];
            float4 mb = mB[d4], pb = pB[d4];
            float4 kA = make_float4(ma.x + pa.x, ma.y + pa.y, ma.z + pa.z, ma.w + pa.w);
            float4 kB = make_float4(mb.x + pb.x, mb.y + pb.y, mb.z + pb.z, mb.w + pb.w);
            dA0 += dot4(kA, qs[qA0][d4]);
            dA1 += dot4(kA, qs[qA1][d4]);
            dA2 += dot4(kA, qs[qA2][d4]);
            dB0 += dot4(kB, qs[qB0][d4]);
            dB1 += dot4(kB, qs[qB1][d4]);
            dB2 += dot4(kB, qs[qB2][d4]);
        }
        #pragma unroll
        for (int o = 16; o > 0; o >>= 1) {
            dA0 += __shfl_xor_sync(0xffffffffu, dA0, o);
            dA1 += __shfl_xor_sync(0xffffffffu, dA1, o);
            dA2 += __shfl_xor_sync(0xffffffffu, dA2, o);
            dB0 += __shfl_xor_sync(0xffffffffu, dB0, o);
            dB1 += __shfl_xor_sync(0xffffffffu, dB1, o);
            dB2 += __shfl_xor_sync(0xffffffffu, dB2, o);
        }
        if (lane == 0) {
            const int u = tA & (SEG - 1);
            if (rA >= 0     && rA < G)     sp[rA][u + 64]     = dA0 * scale;
            if (rA + 1 >= 0 && rA + 1 < G) sp[rA + 1][u + 32] = dA1 * scale;
            if (rA + 2 >= 0 && rA + 2 < G) sp[rA + 2][u]      = dA2 * scale;
        } else if (lane == 1 && hasB) {
            const int u = tB & (SEG - 1);
            if (rB >= 0     && rB < G)     sp[rB][u + 64]     = dB0 * scale;
            if (rB + 1 >= 0 && rB + 1 < G) sp[rB + 1][u + 32] = dB1 * scale;
            if (rB + 2 >= 0 && rB + 2 < G) sp[rB + 2][u]      = dB2 * scale;
        }
    }
    __syncthreads();

    if (warp < G) {
        const int qi = warp;
        float v0 = sp[qi][lane];
        float v1 = sp[qi][lane + 32];
        float v2 = sp[qi][lane + 64];
        float m = fmaxf(v0, fmaxf(v1, v2));
        #pragma unroll
        for (int o = 16; o > 0; o >>= 1)
            m = fmaxf(m, __shfl_xor_sync(0xffffffffu, m, o));
        float e0 = __expf(v0 - m);
        float e1 = __expf(v1 - m);
        float e2 = __expf(v2 - m);
        float ssum = e0 + e1 + e2;
        #pragma unroll
        for (int o = 16; o > 0; o >>= 1)
            ssum += __shfl_xor_sync(0xffffffffu, ssum, o);
        sp[qi][lane]      = e0;
        sp[qi][lane + 32] = e1;
        sp[qi][lane + 64] = e2;
        if (lane == 0) invd[qi] = 1.f / ssum;
    }
    __syncthreads();

    {
        const int dc = tid;
        float acc0 = 0.f, acc1 = 0.f, acc2 = 0.f, acc3 = 0.f;
        const int si_lo = (q0 == 0) ? 1 : 0;
        const int si_hi = min(6, 513 - q0);
        for (int si = si_lo; si < si_hi; si++) {
            const int a = q0 - 1 + si;
            const float* mrow = mem + (size_t)a * SEG * D + dc;
            const bool p0 = (si <= 2);
            const bool p1 = (si >= 1 && si <= 3);
            const bool p2 = (si >= 2 && si <= 4);
            const bool p3 = (si >= 3);
            #pragma unroll
            for (int uu = 0; uu < SEG; uu += 4) {
                float mv0 = mrow[(size_t)(uu + 0) * D];
                float mv1 = mrow[(size_t)(uu + 1) * D];
                float mv2 = mrow[(size_t)(uu + 2) * D];
                float mv3 = mrow[(size_t)(uu + 3) * D];
                if (p0) {
                    const float* w = &sp[0][si * 32 + uu];
                    acc0 = fmaf(w[0], mv0, acc0); acc0 = fmaf(w[1], mv1, acc0);
                    acc0 = fmaf(w[2], mv2, acc0); acc0 = fmaf(w[3], mv3, acc0);
                }
                if (p1) {
                    const float* w = &sp[1][(si - 1) * 32 + uu];
                    acc1 = fmaf(w[0], mv0, acc1); acc1 = fmaf(w[1], mv1, acc1);
                    acc1 = fmaf(w[2], mv2, acc1); acc1 = fmaf(w[3], mv3, acc1);
                }
                if (p2) {
                    const float* w = &sp[2][(si - 2) * 32 + uu];
                    acc2 = fmaf(w[0], mv0, acc2); acc2 = fmaf(w[1], mv1, acc2);
                    acc2 = fmaf(w[2], mv2, acc2); acc2 = fmaf(w[3], mv3, acc2);
                }
                if (p3) {
                    const float* w = &sp[3][(si - 3) * 32 + uu];
                    acc3 = fmaf(w[0], mv0, acc3); acc3 = fmaf(w[1], mv1, acc3);
                    acc3 = fmaf(w[2], mv2, acc3); acc3 = fmaf(w[3], mv3, acc3);
                }
            }
        }
        acc0 = fmaxf(acc0 * invd[0], 0.f);
        acc1 = fmaxf(acc1 * invd[1], 0.f);
        acc2 = fmaxf(acc2 * invd[2], 0.f);
        acc3 = fmaxf(acc3 * invd[3], 0.f);
        g_rctx_h[(size_t)(q0 + 0) * D + dc] = __float2half_rn(acc0);
        g_rctx_h[(size_t)(q0 + 1) * D + dc] = __float2half_rn(acc1);
        g_rctx_h[(size_t)(q0 + 2) * D + dc] = __float2half_rn(acc2);
        g_rctx_h[(size_t)(q0 + 3) * D + dc] = __float2half_rn(acc3);
    }
}

// ============================================================
// FP16 tensor-core GEMM, 3-stage cp.async pipeline, 256 threads.
// MODE 1: relu(acc + bias) -> fp16 to (half*)C
// MODE 2: atomicAdd fp32 accumulate into (float*)C (pre-initialized)
// ============================================================
template <int BN, int KSPLIT, int MODE>
__global__ __launch_bounds__(256) void gemm_h(
    const __half* __restrict__ A, const __half* __restrict__ W,
    const float* __restrict__ bias, void* __restrict__ C,
    int M, int N, int K)
{
    constexpr int BM = 64, BK = 64;
    constexpr int NWN = BN / 32;
    constexpr int NWM = 8 / NWN;
    constexpr int WM  = BM / NWM;
    constexpr int TM  = WM / 16;
    constexpr int LDA = BK + 8;
    constexpr int LDC = BN + 4;

    __shared__ union SmemU {
        struct { __half A[3][BM][LDA]; __half B[3][BN][LDA]; } s;
        float Cs[BM][LDC];
    } sm;

    const int tid  = threadIdx.x;
    const int warp = tid >> 5;
    const int wm = warp / NWN, wn = warp % NWN;
    const int col0 = blockIdx.x * BN;
    const int row0 = blockIdx.y * BM;
    const int Kloc = K / KSPLIT;
    const int kbase = blockIdx.z * Kloc;

    wmma::fragment<wmma::accumulator, 16, 16, 16, float> acc[TM][2];
    #pragma unroll
    for (int i = 0; i < TM; i++)
        #pragma unroll
        for (int j = 0; j < 2; j++)
            wmma::fill_fragment(acc[i][j], 0.f);

    const int NIT = Kloc / BK;

    auto load_tile = [&](int it, int st) {
        const int k0 = kbase + it * BK;
        #pragma unroll
        for (int i = tid; i < BM * (BK / 8); i += 256) {
            int r = i >> 3, c = (i & 7) * 8;
            cp_async16(&sm.s.A[st][r][c], &A[(size_t)(row0 + r) * K + k0 + c]);
        }
        #pragma unroll
        for (int i = tid; i < BN * (BK / 8); i += 256) {
            int r = i >> 3, c = (i & 7) * 8;
            cp_async16(&sm.s.B[st][r][c], &W[(size_t)(col0 + r) * K + k0 + c]);
        }
    };

    load_tile(0, 0);
    cp_commit();
    if (NIT > 1) load_tile(1, 1);
    cp_commit();

    for (int it = 0; it < NIT; it++) {
        if (it + 2 < NIT) load_tile(it + 2, (it + 2) % 3);
        cp_commit();
        cp_wait2();
        __syncthreads();

        const int st = it % 3;
        #pragma unroll
        for (int kk = 0; kk < BK; kk += 16) {
            wmma::fragment<wmma::matrix_a, 16, 16, 16, __half, wmma::row_major> fa[TM];
            wmma::fragment<wmma::matrix_b, 16, 16, 16, __half, wmma::col_major> fb[2];
            #pragma unroll
            for (int i = 0; i < TM; i++)
                wmma::load_matrix_sync(fa[i], &sm.s.A[st][wm * WM + i * 16][kk], LDA);
            #pragma unroll
            for (int j = 0; j < 2; j++)
                wmma::load_matrix_sync(fb[j], &sm.s.B[st][wn * 32 + j * 16][kk], LDA);
            #pragma unroll
            for (int i = 0; i < TM; i++)
                #pragma unroll
                for (int j = 0; j < 2; j++)
                    wmma::mma_sync(acc[i][j], fa[i], fb[j], acc[i][j]);
        }
        __syncthreads();
    }

    #pragma unroll
    for (int i = 0; i < TM; i++)
        #pragma unroll
        for (int j = 0; j < 2; j++)
            wmma::store_matrix_sync(&sm.Cs[wm * WM + i * 16][wn * 32 + j * 16],
                                    acc[i][j], LDC, wmma::mem_row_major);
    __syncthreads();

    if (MODE == 2) {
        float* Co = (float*)C;
        #pragma unroll
        for (int i = tid; i < BM * (BN / 4); i += 256) {
            int r = i / (BN / 4), c = (i % (BN / 4)) * 4;
            float4 v = *(float4*)&sm.Cs[r][c];
            float* dst = &Co[(size_t)(row0 + r) * N + col0 + c];
            atomicAdd(dst + 0, v.x);
            atomicAdd(dst + 1, v.y);
            atomicAdd(dst + 2, v.z);
            atomicAdd(dst + 3, v.w);
        }
    } else {
        __half* Co = (__half*)C;
        #pragma unroll
        for (int i = tid; i < BM * (BN / 4); i += 256) {
            int r = i / (BN / 4), c = (i % (BN / 4)) * 4;
            float4 v = *(float4*)&sm.Cs[r][c];
            float4 b4 = *(const float4*)&bias[col0 + c];
            v.x = fmaxf(v.x + b4.x, 0.f);
            v.y = fmaxf(v.y + b4.y, 0.f);
            v.z = fmaxf(v.z + b4.z, 0.f);
            v.w = fmaxf(v.w + b4.w, 0.f);
            __half2* o2 = (__half2*)&Co[(size_t)(row0 + r) * N + col0 + c];
            o2[0] = __floats2half2_rn(v.x, v.y);
            o2[1] = __floats2half2_rn(v.z, v.w);
        }
    }
}

// ============================================================
// LayerNorm: warp-per-row, barrier-free, smem-free.
// Reads pre-accumulated v from acc (already includes residual+bias).
// WH: also write fp16 x to g_xh AND acc_next = x + b_next (gemm5 init).
// ============================================================
template <bool WH>
__global__ __launch_bounds__(128) void ln_kernel(
    const float* __restrict__ acc,
    const float* __restrict__ g, const float* __restrict__ be,
    float* __restrict__ out,
    const float* __restrict__ b_next, float* __restrict__ acc_next)
{
    const int warp = threadIdx.x >> 5, lane = threadIdx.x & 31;
    const int row  = blockIdx.x * 4 + warp;
    const size_t base = (size_t)row * (D / 4);

    float4 v[4];
    #pragma unroll
    for (int j = 0; j < 4; j++)
        v[j] = ((const float4*)acc)[base + lane + 32 * j];

    float s1 = 0.f, s2 = 0.f;
    #pragma unroll
    for (int j = 0; j < 4; j++) {
        s1 += v[j].x + v[j].y + v[j].z + v[j].w;
        s2 += v[j].x * v[j].x + v[j].y * v[j].y + v[j].z * v[j].z + v[j].w * v[j].w;
    }
    #pragma unroll
    for (int o = 16; o > 0; o >>= 1) {
        s1 += __shfl_xor_sync(0xffffffffu, s1, o);
        s2 += __shfl_xor_sync(0xffffffffu, s2, o);
    }
    const float mu = s1 * (1.0f / D);
    const float var = s2 * (1.0f / D) - mu * mu;
    const float rstd = rsqrtf(fmaxf(var, 0.f) + 1e-5f);

    #pragma unroll
    for (int j = 0; j < 4; j++) {
        const int c4 = lane + 32 * j;
        float4 g4 = ((const float4*)g)[c4];
        float4 b4 = ((const float4*)be)[c4];
        float4 o4;
        o4.x = (v[j].x - mu) * rstd * g4.x + b4.x;
        o4.y = (v[j].y - mu) * rstd * g4.y + b4.y;
        o4.z = (v[j].z - mu) * rstd * g4.z + b4.z;
        o4.w = (v[j].w - mu) * rstd * g4.w + b4.w;
        ((float4*)out)[base + c4] = o4;
        if (WH) {
            __half2* xh2 = (__half2*)g_xh + (base + c4) * 2;
            xh2[0] = __floats2half2_rn(o4.x, o4.y);
            xh2[1] = __floats2half2_rn(o4.z, o4.w);
            float4 bn = ((const float4*)b_next)[c4];
            ((float4*)acc_next)[base + c4] =
                make_float4(o4.x + bn.x, o4.y + bn.y, o4.z + bn.z, o4.w + bn.w);
        }
    }
}

// ============================================================
extern "C" void kernel_launch(void* const* d_in, const int* in_sizes, int n_in,
                              void* d_out, int out_size)
{
    const float* tgt  = (const float*)d_in[0];
    const float* mem  = (const float*)d_in[1];
    const float* pos  = (const float*)d_in[2];
    const float* qpos = (const float*)d_in[3];
    const int*   aidx = (const int*)d_in[4];
    const float* Wt2  = (const float*)d_in[5];
    const float* bt2  = (const float*)d_in[6];
    const float* W1   = (const float*)d_in[7];
    const float* b1   = (const float*)d_in[8];
    const float* W2   = (const float*)d_in[9];
    const float* b2   = (const float*)d_in[10];
    const float* g2   = (const float*)d_in[11];
    const float* be2  = (const float*)d_in[12];
    const float* g3   = (const float*)d_in[13];
    const float* be3  = (const float*)d_in[14];
    float* out = (float*)d_out;

    __half *rctx_p, *xh_p, *h_p, *wh_p;
    float *x_p, *acc_p;
    cudaGetSymbolAddress((void**)&rctx_p, g_rctx_h);
    cudaGetSymbolAddress((void**)&xh_p,   g_xh);
    cudaGetSymbolAddress((void**)&h_p,    g_h);
    cudaGetSymbolAddress((void**)&wh_p,   g_wh);
    cudaGetSymbolAddress((void**)&x_p,    g_x);
    cudaGetSymbolAddress((void**)&acc_p,  g_acc);

    const __half* whT2 = wh_p;
    const __half* wh1  = wh_p + D * D;
    const __half* wh2  = wh_p + D * D + (size_t)DFF * D;
    float* acc2 = acc_p;              // tgt2 path accumulator
    float* acc5 = acc_p + S * D;      // ffn path accumulator

    // 0) weights fp32->fp16; acc2 = tgt + bt2
    cvt_kernel<<<dim3(128, 4), 256>>>(Wt2, W1, W2, tgt, bt2);

    // 1) attention -> relu(ctx) fp16
    attn_kernel<<<S / G, 512>>>(tgt, mem, pos, qpos, aidx);

    // 2) acc2 += rctx @ Wt2^T   [512,512,K=512], splitK=2, RED-add
    gemm_h<64, 2, 2><<<dim3(D / 64, S / 64, 2), 256>>>(rctx_p, whT2, nullptr, acc2, S, D, D);

    // 3) x = LN(acc2); also fp16 x and acc5 = x + b2
    ln_kernel<true><<<S / 4, 128>>>(acc2, g2, be2, x_p, b2, acc5);

    // 4) h = relu(x @ W1^T + b1) fp16   [512,2048,K=512]
    gemm_h<128, 1, 1><<<dim3(DFF / 128, S / 64, 1), 256>>>(xh_p, wh1, b1, h_p, S, DFF, D);

    // 5) acc5 += h @ W2^T   [512,512,K=2048], splitK=2, RED-add
    gemm_h<64, 2, 2><<<dim3(D / 64, S / 64, 2), 256>>>(h_p, wh2, nullptr, acc5, S, D, DFF);

    // 6) out = LN(acc5)
    ln_kernel<false><<<S / 4, 128>>>(acc5, g3, be3, out, nullptr, nullptr);
}